// round 3
// baseline (speedup 1.0000x reference)
#include <cuda_runtime.h>
#include <cuda_bf16.h>

#define N_NODES 100000
#define N_EDGES 1600000
#define N_FEAT 128
#define HIDN 256
#define N_CLASSES 47
#define NCP 48   // padded classes (for float4 scatter)

// Scratch (device globals: allocation-free rule)
__device__ __align__(16) float g_agg1[N_NODES * N_FEAT];   // 51.2 MB
__device__ __align__(16) float g_deg [N_NODES];            // 0.4 MB
__device__ __align__(16) float g_h   [N_NODES * HIDN];     // 102.4 MB
__device__ __align__(16) float g_hl  [N_NODES * NCP];      // 19.2 MB
__device__ __align__(16) float g_agg2[N_NODES * NCP];      // 19.2 MB

// ---------------------------------------------------------------------------
__global__ void zero_kernel(float4* __restrict__ p, int n4) {
    int i = blockIdx.x * blockDim.x + threadIdx.x;
    if (i < n4) p[i] = make_float4(0.f, 0.f, 0.f, 0.f);
}

__global__ void invdeg_kernel(float* __restrict__ deg, int n) {
    int i = blockIdx.x * blockDim.x + threadIdx.x;
    if (i < n) deg[i] = 1.0f / fmaxf(deg[i], 1.0f);
}

// ---------------------------------------------------------------------------
// One warp per edge (F=128 -> 32 float4s, one per lane). Gather feat[src]
// (L2-resident), vector-RED into agg[dst]. Also counts degree.
__global__ void scatter_add_128(const float* __restrict__ feat,
                                const int* __restrict__ src,
                                const int* __restrict__ dst,
                                float* __restrict__ agg,
                                float* __restrict__ deg,
                                int E) {
    int gw   = (blockIdx.x * blockDim.x + threadIdx.x) >> 5;
    int lane = threadIdx.x & 31;
    if (gw >= E) return;
    int s = __ldg(src + gw);
    int d = __ldg(dst + gw);
    const float4* fs = (const float4*)(feat + (size_t)s * N_FEAT);
    float4*       fd = (float4*)(agg  + (size_t)d * N_FEAT);
    float4 v = __ldg(fs + lane);
    asm volatile("red.global.add.v4.f32 [%0], {%1, %2, %3, %4};"
                 :: "l"(fd + lane), "f"(v.x), "f"(v.y), "f"(v.z), "f"(v.w)
                 : "memory");
    if (lane == 0) atomicAdd(&deg[d], 1.0f);
}

// One thread per float4 (48-wide rows -> 12 float4s per edge).
__global__ void scatter_add_48(const float* __restrict__ feat,
                               const int* __restrict__ src,
                               const int* __restrict__ dst,
                               float* __restrict__ agg,
                               int total) {  // = E * 12
    int gid = blockIdx.x * blockDim.x + threadIdx.x;
    if (gid >= total) return;
    int e = gid / 12;
    int c = gid % 12;
    int s = __ldg(src + e);
    int d = __ldg(dst + e);
    float4 v = __ldg((const float4*)(feat + (size_t)s * NCP) + c);
    float4* fd = (float4*)(agg + (size_t)d * NCP) + c;
    asm volatile("red.global.add.v4.f32 [%0], {%1, %2, %3, %4};"
                 :: "l"(fd), "f"(v.x), "f"(v.y), "f"(v.z), "f"(v.w)
                 : "memory");
}

// ---------------------------------------------------------------------------
// Layer-1 fused GEMM:  h = relu( [agg*invdeg | x] @ [Wl ; Wr] + bias )
// Virtual A is [M, 2*Kh]. Classic SMEM-tiled fp32 GEMM.
template<int BM, int BN, int BK, int TM, int TN>
__global__ void __launch_bounds__((BM / TM) * (BN / TN))
sage_gemm1(const float* __restrict__ agg,
           const float* __restrict__ xin,
           const float* __restrict__ invdeg,
           const float* __restrict__ Wl,
           const float* __restrict__ Wr,
           const float* __restrict__ bias,
           float* __restrict__ outp,
           int M, int N, int Kh) {
    constexpr int NTH = (BM / TM) * (BN / TN);
    __shared__ float As[BK][BM + 4];
    __shared__ float Bs[BK][BN];

    const int tid = threadIdx.x;
    const int m0  = blockIdx.x * BM;
    const int n0  = blockIdx.y * BN;
    const int tr  = tid / (BN / TN);
    const int tc  = tid % (BN / TN);

    float acc[TM][TN];
#pragma unroll
    for (int i = 0; i < TM; ++i)
#pragma unroll
        for (int j = 0; j < TN; ++j) acc[i][j] = 0.f;

    constexpr int A_F4_PER_ROW = BK / 4;
    constexpr int A_ROW_STEP   = NTH / A_F4_PER_ROW;
    constexpr int A_PER        = (BM * BK / 4) / NTH;
    const int aRow = tid / A_F4_PER_ROW;
    const int aQ   = tid % A_F4_PER_ROW;

    float myInv[A_PER];
#pragma unroll
    for (int r = 0; r < A_PER; ++r) {
        int grow = m0 + aRow + r * A_ROW_STEP;
        myInv[r] = (grow < M) ? invdeg[grow] : 0.f;
    }

    constexpr int B_STEP = NTH / BN;
    const int bCol  = tid % BN;
    const int bRow0 = tid / BN;

    const int nK = (2 * Kh) / BK;
    for (int kt = 0; kt < nK; ++kt) {
        const int k0 = kt * BK;
#pragma unroll
        for (int r = 0; r < A_PER; ++r) {
            int row  = aRow + r * A_ROW_STEP;
            int grow = m0 + row;
            int kg   = k0 + aQ * 4;
            float4 v = make_float4(0.f, 0.f, 0.f, 0.f);
            if (grow < M) {
                if (kg < Kh) {
                    v = *(const float4*)(agg + (size_t)grow * Kh + kg);
                    float id = myInv[r];
                    v.x *= id; v.y *= id; v.z *= id; v.w *= id;
                } else {
                    v = *(const float4*)(xin + (size_t)grow * Kh + (kg - Kh));
                }
            }
            int kl = aQ * 4;
            As[kl + 0][row] = v.x;
            As[kl + 1][row] = v.y;
            As[kl + 2][row] = v.z;
            As[kl + 3][row] = v.w;
        }
#pragma unroll
        for (int r = 0; r < BK / B_STEP; ++r) {
            int kl = bRow0 + r * B_STEP;
            int kg = k0 + kl;
            float v = 0.f;
            int col = n0 + bCol;
            if (col < N) {
                v = (kg < Kh) ? Wl[(size_t)kg * N + col]
                              : Wr[(size_t)(kg - Kh) * N + col];
            }
            Bs[kl][bCol] = v;
        }
        __syncthreads();
#pragma unroll
        for (int k = 0; k < BK; ++k) {
            float ra[TM], rb[TN];
#pragma unroll
            for (int i = 0; i < TM; ++i) ra[i] = As[k][tr * TM + i];
#pragma unroll
            for (int j = 0; j < TN; ++j) rb[j] = Bs[k][tc * TN + j];
#pragma unroll
            for (int i = 0; i < TM; ++i)
#pragma unroll
                for (int j = 0; j < TN; ++j) acc[i][j] += ra[i] * rb[j];
        }
        __syncthreads();
    }
#pragma unroll
    for (int i = 0; i < TM; ++i) {
        int grow = m0 + tr * TM + i;
        if (grow >= M) continue;
#pragma unroll
        for (int j = 0; j < TN; ++j) {
            int gcol = n0 + tc * TN + j;
            if (gcol >= N) continue;
            float v = acc[i][j] + bias[gcol];
            outp[(size_t)grow * N + gcol] = fmaxf(v, 0.f);
        }
    }
}

// ---------------------------------------------------------------------------
// Plain GEMM: out[M, ldOut] = A[M, K] @ B[K, Nb] (+ bias) (+ aggAdd*invdeg)
// Writes cols [0, Nw); B cols >= Nb read as 0. AGG: epilogue adds
// aggAdd[row*ldAgg+col] * invdeg[row] (the commuted mean-aggregate term).
template<int BM, int BN, int BK, int TM, int TN, bool AGG>
__global__ void __launch_bounds__((BM / TM) * (BN / TN))
gemm_plain(const float* __restrict__ A,
           const float* __restrict__ B,
           const float* __restrict__ bias,     // nullable
           const float* __restrict__ aggAdd,   // used iff AGG
           const float* __restrict__ invdeg,   // used iff AGG
           float* __restrict__ outp,
           int M, int Nb, int Nw, int K, int ldOut, int ldAgg) {
    constexpr int NTH = (BM / TM) * (BN / TN);
    __shared__ float As[BK][BM + 4];
    __shared__ float Bs[BK][BN];

    const int tid = threadIdx.x;
    const int m0  = blockIdx.x * BM;
    const int n0  = blockIdx.y * BN;
    const int tr  = tid / (BN / TN);
    const int tc  = tid % (BN / TN);

    float acc[TM][TN];
#pragma unroll
    for (int i = 0; i < TM; ++i)
#pragma unroll
        for (int j = 0; j < TN; ++j) acc[i][j] = 0.f;

    constexpr int A_F4_PER_ROW = BK / 4;
    constexpr int A_ROW_STEP   = NTH / A_F4_PER_ROW;
    constexpr int A_PER        = (BM * BK / 4) / NTH;
    const int aRow = tid / A_F4_PER_ROW;
    const int aQ   = tid % A_F4_PER_ROW;

    constexpr int B_STEP = NTH / BN;
    const int bCol  = tid % BN;
    const int bRow0 = tid / BN;

    const int nK = K / BK;
    for (int kt = 0; kt < nK; ++kt) {
        const int k0 = kt * BK;
#pragma unroll
        for (int r = 0; r < A_PER; ++r) {
            int row  = aRow + r * A_ROW_STEP;
            int grow = m0 + row;
            int kg   = k0 + aQ * 4;
            float4 v = make_float4(0.f, 0.f, 0.f, 0.f);
            if (grow < M)
                v = *(const float4*)(A + (size_t)grow * K + kg);
            int kl = aQ * 4;
            As[kl + 0][row] = v.x;
            As[kl + 1][row] = v.y;
            As[kl + 2][row] = v.z;
            As[kl + 3][row] = v.w;
        }
#pragma unroll
        for (int r = 0; r < BK / B_STEP; ++r) {
            int kl = bRow0 + r * B_STEP;
            int kg = k0 + kl;
            float v = 0.f;
            int col = n0 + bCol;
            if (col < Nb)
                v = B[(size_t)kg * Nb + col];
            Bs[kl][bCol] = v;
        }
        __syncthreads();
#pragma unroll
        for (int k = 0; k < BK; ++k) {
            float ra[TM], rb[TN];
#pragma unroll
            for (int i = 0; i < TM; ++i) ra[i] = As[k][tr * TM + i];
#pragma unroll
            for (int j = 0; j < TN; ++j) rb[j] = Bs[k][tc * TN + j];
#pragma unroll
            for (int i = 0; i < TM; ++i)
#pragma unroll
                for (int j = 0; j < TN; ++j) acc[i][j] += ra[i] * rb[j];
        }
        __syncthreads();
    }
#pragma unroll
    for (int i = 0; i < TM; ++i) {
        int grow = m0 + tr * TM + i;
        if (grow >= M) continue;
        float id = AGG ? invdeg[grow] : 0.f;
#pragma unroll
        for (int j = 0; j < TN; ++j) {
            int gcol = n0 + tc * TN + j;
            if (gcol >= Nw) continue;
            float v = acc[i][j];
            if (bias != nullptr && gcol < Nb) v += bias[gcol];
            if (AGG && gcol < Nb)
                v += aggAdd[(size_t)grow * ldAgg + gcol] * id;
            outp[(size_t)grow * ldOut + gcol] = v;
        }
    }
}

// ---------------------------------------------------------------------------
extern "C" void kernel_launch(void* const* d_in, const int* in_sizes, int n_in,
                              void* d_out, int out_size) {
    const float* x   = (const float*)d_in[0];
    const int*   ei  = (const int*)  d_in[1];
    const float* Wl1 = (const float*)d_in[2];
    const float* Wr1 = (const float*)d_in[3];
    const float* b1  = (const float*)d_in[4];
    const float* Wl2 = (const float*)d_in[5];
    const float* Wr2 = (const float*)d_in[6];
    const float* b2  = (const float*)d_in[7];
    float* out = (float*)d_out;

    const int* src = ei;
    const int* dst = ei + N_EDGES;

    float *agg1, *deg, *h, *hl, *agg2;
    cudaGetSymbolAddress((void**)&agg1, g_agg1);
    cudaGetSymbolAddress((void**)&deg,  g_deg);
    cudaGetSymbolAddress((void**)&h,    g_h);
    cudaGetSymbolAddress((void**)&hl,   g_hl);
    cudaGetSymbolAddress((void**)&agg2, g_agg2);

    // 1. zero scratch accumulators
    {
        int n4 = N_NODES * N_FEAT / 4;
        zero_kernel<<<(n4 + 511) / 512, 512>>>((float4*)agg1, n4);
        n4 = N_NODES * NCP / 4;
        zero_kernel<<<(n4 + 511) / 512, 512>>>((float4*)agg2, n4);
        n4 = N_NODES / 4;
        zero_kernel<<<(n4 + 511) / 512, 512>>>((float4*)deg, n4);
    }

    // 2. layer-1 scatter (also counts degree)
    {
        long long threads = (long long)N_EDGES * 32;
        int blocks = (int)((threads + 511) / 512);
        scatter_add_128<<<blocks, 512>>>(x, src, dst, agg1, deg, N_EDGES);
    }

    // 3. deg -> 1/max(deg,1) in place
    invdeg_kernel<<<(N_NODES + 255) / 256, 256>>>(deg, N_NODES);

    // 4. layer-1 fused GEMM + bias + ReLU -> h   [M=100k, N=256, K=2*128]
    {
        dim3 grid((N_NODES + 127) / 128, HIDN / 64);
        sage_gemm1<128, 64, 16, 8, 8><<<grid, 128>>>(
            agg1, x, deg, Wl1, Wr1, b1, h, N_NODES, HIDN, N_FEAT);
    }

    // 5. hl = h @ Wl2 (padded to 48 cols; col 47 = 0)   [N=47, K=256]
    {
        dim3 grid((N_NODES + 127) / 128, 1);
        gemm_plain<128, 64, 16, 8, 8, false><<<grid, 128>>>(
            h, Wl2, nullptr, nullptr, nullptr, hl,
            N_NODES, N_CLASSES, NCP, HIDN, NCP, 0);
    }

    // 6. layer-2 scatter on 48-wide hl (linearity: agg commutes with Wl2)
    {
        int total = N_EDGES * 12;
        scatter_add_48<<<(total + 511) / 512, 512>>>(hl, src, dst, agg2, total);
    }

    // 7. out = h @ Wr2 + b2 + agg2*invdeg   [N=47, K=256]
    {
        dim3 grid((N_NODES + 127) / 128, 1);
        gemm_plain<128, 64, 16, 8, 8, true><<<grid, 128>>>(
            h, Wr2, b2, agg2, deg, out,
            N_NODES, N_CLASSES, N_CLASSES, HIDN, N_CLASSES, NCP);
    }
}

// round 17
// speedup vs baseline: 1.4830x; 1.4830x over previous
#include <cuda_runtime.h>
#include <cuda_bf16.h>

#define N_NODES 100000
#define N_EDGES 1600000
#define N_FEAT 128
#define HIDN 256
#define N_CLASSES 47
#define NCP 48   // padded classes
#define NW2 96   // packed layer-2 weight width (48 + 48)

// Scratch (device globals: allocation-free rule)
__device__ __align__(16) float g_agg1[N_NODES * N_FEAT];   // 51.2 MB
__device__ __align__(16) float g_deg [N_NODES];            // 0.4 MB
__device__ __align__(16) float g_h   [N_NODES * HIDN];     // 102.4 MB
__device__ __align__(16) float g_hl  [N_NODES * NCP];      // 19.2 MB
__device__ __align__(16) float g_hr  [N_NODES * NCP];      // 19.2 MB
__device__ __align__(16) float g_agg2[N_NODES * NCP];      // 19.2 MB
__device__ __align__(16) float g_wcat[HIDN * NW2];         // 96 KB

// ---------------------------------------------------------------------------
__global__ void zero_kernel(float4* __restrict__ p, int n4) {
    int i = blockIdx.x * blockDim.x + threadIdx.x;
    if (i < n4) p[i] = make_float4(0.f, 0.f, 0.f, 0.f);
}

__global__ void invdeg_kernel(float* __restrict__ deg, int n) {
    int i = blockIdx.x * blockDim.x + threadIdx.x;
    if (i < n) deg[i] = 1.0f / fmaxf(deg[i], 1.0f);
}

// Pack [Wl2 | 0 | Wr2 | 0] -> Wcat[HIDN][96]
__global__ void pack_wcat(const float* __restrict__ Wl2,
                          const float* __restrict__ Wr2,
                          float* __restrict__ Wcat) {
    int i = blockIdx.x * blockDim.x + threadIdx.x;
    if (i >= HIDN * NW2) return;
    int k = i / NW2, c = i % NW2;
    float v = 0.f;
    if (c < N_CLASSES)                        v = Wl2[k * N_CLASSES + c];
    else if (c >= NCP && c < NCP + N_CLASSES) v = Wr2[k * N_CLASSES + (c - NCP)];
    Wcat[i] = v;
}

// ---------------------------------------------------------------------------
// Scatter, layer 1. One warp per 4 edges: 4 independent LDG.128 in flight
// (raises MLP from 1 to 4 to cover L2-hit latency), then 4 vector REDs.
#define EPW 4
__global__ void scatter_add_128(const float* __restrict__ feat,
                                const int* __restrict__ src,
                                const int* __restrict__ dst,
                                float* __restrict__ agg,
                                float* __restrict__ deg,
                                int E) {
    int warp = (blockIdx.x * blockDim.x + threadIdx.x) >> 5;
    int lane = threadIdx.x & 31;
    int e0 = warp * EPW;
    if (e0 >= E) return;
    int s[EPW], d[EPW];
#pragma unroll
    for (int i = 0; i < EPW; ++i) {
        int e = e0 + i;
        s[i] = (e < E) ? __ldg(src + e) : -1;
        d[i] = (e < E) ? __ldg(dst + e) : 0;
    }
    float4 v[EPW];
#pragma unroll
    for (int i = 0; i < EPW; ++i)
        if (s[i] >= 0)
            v[i] = __ldg((const float4*)(feat + (size_t)s[i] * N_FEAT) + lane);
#pragma unroll
    for (int i = 0; i < EPW; ++i) {
        if (s[i] < 0) continue;
        float4* fd = (float4*)(agg + (size_t)d[i] * N_FEAT) + lane;
        asm volatile("red.global.add.v4.f32 [%0], {%1, %2, %3, %4};"
                     :: "l"(fd), "f"(v[i].x), "f"(v[i].y), "f"(v[i].z), "f"(v[i].w)
                     : "memory");
        if (lane == 0) atomicAdd(&deg[d[i]], 1.0f);
    }
}

// Scatter, layer 2 (48-wide rows = 12 float4). Each thread handles the same
// column of two distant edges (ILP=2). gid spans (E/2)*12.
__global__ void scatter_add_48(const float* __restrict__ feat,
                               const int* __restrict__ src,
                               const int* __restrict__ dst,
                               float* __restrict__ agg,
                               int E) {
    int gid = blockIdx.x * blockDim.x + threadIdx.x;
    int half = (E / 2) * 12;
    if (gid >= half) return;
    int e1 = gid / 12;
    int c  = gid % 12;
    int e2 = e1 + E / 2;
    int s1 = __ldg(src + e1), d1 = __ldg(dst + e1);
    int s2 = __ldg(src + e2), d2 = __ldg(dst + e2);
    float4 v1 = __ldg((const float4*)(feat + (size_t)s1 * NCP) + c);
    float4 v2 = __ldg((const float4*)(feat + (size_t)s2 * NCP) + c);
    float4* f1 = (float4*)(agg + (size_t)d1 * NCP) + c;
    float4* f2 = (float4*)(agg + (size_t)d2 * NCP) + c;
    asm volatile("red.global.add.v4.f32 [%0], {%1, %2, %3, %4};"
                 :: "l"(f1), "f"(v1.x), "f"(v1.y), "f"(v1.z), "f"(v1.w) : "memory");
    asm volatile("red.global.add.v4.f32 [%0], {%1, %2, %3, %4};"
                 :: "l"(f2), "f"(v2.x), "f"(v2.y), "f"(v2.z), "f"(v2.w) : "memory");
}

// ---------------------------------------------------------------------------
// Layer-1 fused GEMM, double-buffered:
//   h = relu( [agg*invdeg | x] @ [Wl1 ; Wr1] + b1 )
// BM=128, BN=128, BK=16, TM=TN=8, 256 threads.
__global__ void __launch_bounds__(256)
sage_gemm1(const float* __restrict__ agg,
           const float* __restrict__ xin,
           const float* __restrict__ invdeg,
           const float* __restrict__ Wl,
           const float* __restrict__ Wr,
           const float* __restrict__ bias,
           float* __restrict__ outp,
           int M) {
    constexpr int BM = 128, BN = 128, BK = 16;
    __shared__ float As[2][BK][BM + 4];
    __shared__ float Bs[2][BK][BN];

    const int tid = threadIdx.x;
    const int m0  = blockIdx.x * BM;
    const int n0  = blockIdx.y * BN;
    const int tr  = tid / 16;          // 0..15 (rows tr*8..)
    const int tc  = tid % 16;          // 0..15 (cols tc*8..)

    const int aQ   = tid & 3;          // k-quad: k = aQ*4..aQ*4+3
    const int aRow = tid >> 2;         // 0..63; rows aRow, aRow+64
    const int bQ   = tid & 31;         // col quad: col = bQ*4
    const int bRow = tid >> 5;         // 0..7; rows bRow, bRow+8

    float inv0 = (m0 + aRow      < M) ? invdeg[m0 + aRow]      : 0.f;
    float inv1 = (m0 + aRow + 64 < M) ? invdeg[m0 + aRow + 64] : 0.f;

    float acc[8][8];
#pragma unroll
    for (int i = 0; i < 8; ++i)
#pragma unroll
        for (int j = 0; j < 8; ++j) acc[i][j] = 0.f;

    float4 pa[2], pb[2];

    auto loadA = [&](int kt, float4* va) {
        int kg = kt * BK + aQ * 4;
#pragma unroll
        for (int r = 0; r < 2; ++r) {
            int grow = m0 + aRow + r * 64;
            float4 v = make_float4(0.f, 0.f, 0.f, 0.f);
            if (grow < M) {
                if (kg < N_FEAT) {
                    v = *(const float4*)(agg + (size_t)grow * N_FEAT + kg);
                    float id = r ? inv1 : inv0;
                    v.x *= id; v.y *= id; v.z *= id; v.w *= id;
                } else {
                    v = *(const float4*)(xin + (size_t)grow * N_FEAT + (kg - N_FEAT));
                }
            }
            va[r] = v;
        }
    };
    auto loadB = [&](int kt, float4* vb) {
#pragma unroll
        for (int r = 0; r < 2; ++r) {
            int kg  = kt * BK + bRow + r * 8;
            int col = n0 + bQ * 4;
            vb[r] = (kg < N_FEAT)
                ? *(const float4*)(Wl + (size_t)kg * HIDN + col)
                : *(const float4*)(Wr + (size_t)(kg - N_FEAT) * HIDN + col);
        }
    };
    auto storeT = [&](int buf, const float4* va, const float4* vb) {
#pragma unroll
        for (int r = 0; r < 2; ++r) {
            int row = aRow + r * 64, kl = aQ * 4;
            As[buf][kl + 0][row] = va[r].x;
            As[buf][kl + 1][row] = va[r].y;
            As[buf][kl + 2][row] = va[r].z;
            As[buf][kl + 3][row] = va[r].w;
        }
#pragma unroll
        for (int r = 0; r < 2; ++r)
            *(float4*)&Bs[buf][bRow + r * 8][bQ * 4] = vb[r];
    };

    const int nK = (2 * N_FEAT) / BK;   // 16
    loadA(0, pa); loadB(0, pb);
    storeT(0, pa, pb);
    __syncthreads();

    for (int kt = 0; kt < nK; ++kt) {
        int cur = kt & 1;
        if (kt + 1 < nK) { loadA(kt + 1, pa); loadB(kt + 1, pb); }
#pragma unroll
        for (int k = 0; k < BK; ++k) {
            float4 a0 = *(const float4*)&As[cur][k][tr * 8];
            float4 a1 = *(const float4*)&As[cur][k][tr * 8 + 4];
            float4 b0 = *(const float4*)&Bs[cur][k][tc * 8];
            float4 b1 = *(const float4*)&Bs[cur][k][tc * 8 + 4];
            float ra[8] = {a0.x, a0.y, a0.z, a0.w, a1.x, a1.y, a1.z, a1.w};
            float rb[8] = {b0.x, b0.y, b0.z, b0.w, b1.x, b1.y, b1.z, b1.w};
#pragma unroll
            for (int i = 0; i < 8; ++i)
#pragma unroll
                for (int j = 0; j < 8; ++j) acc[i][j] += ra[i] * rb[j];
        }
        if (kt + 1 < nK) storeT(1 - cur, pa, pb);
        __syncthreads();
    }

    // epilogue: bias + relu, float4 stores (HIDN=256 aligned)
#pragma unroll
    for (int i = 0; i < 8; ++i) {
        int grow = m0 + tr * 8 + i;
        if (grow >= M) continue;
        int gcol = n0 + tc * 8;
#pragma unroll
        for (int j = 0; j < 8; ++j)
            acc[i][j] = fmaxf(acc[i][j] + __ldg(bias + gcol + j), 0.f);
        float* dst = outp + (size_t)grow * HIDN + gcol;
        *(float4*)dst       = make_float4(acc[i][0], acc[i][1], acc[i][2], acc[i][3]);
        *(float4*)(dst + 4) = make_float4(acc[i][4], acc[i][5], acc[i][6], acc[i][7]);
    }
}

// ---------------------------------------------------------------------------
// Layer-2 combined GEMM, double-buffered: [hl | hr] = h @ Wcat
// BM=128, BN=96, BK=16, TM=8, TN=6, 256 threads. Cols 0..47 -> hl, 48..95 -> hr.
__global__ void __launch_bounds__(256)
sage_gemm2(const float* __restrict__ A,      // h [M, 256]
           const float* __restrict__ B,      // Wcat [256, 96]
           float* __restrict__ hl,
           float* __restrict__ hr,
           int M) {
    constexpr int BM = 128, BN = NW2, BK = 16, K = HIDN;
    __shared__ float As[2][BK][BM + 4];
    __shared__ float Bs[2][BK][BN];

    const int tid = threadIdx.x;
    const int m0  = blockIdx.x * BM;
    const int tr  = tid / 16;          // 0..15
    const int tc  = tid % 16;          // 0..15 (cols tc*6..)

    const int aQ   = tid & 3;
    const int aRow = tid >> 2;

    float acc[8][6];
#pragma unroll
    for (int i = 0; i < 8; ++i)
#pragma unroll
        for (int j = 0; j < 6; ++j) acc[i][j] = 0.f;

    float4 pa[2];
    float  pb[6];

    auto loadA = [&](int kt, float4* va) {
        int kg = kt * BK + aQ * 4;
#pragma unroll
        for (int r = 0; r < 2; ++r) {
            int grow = m0 + aRow + r * 64;
            va[r] = (grow < M) ? *(const float4*)(A + (size_t)grow * K + kg)
                               : make_float4(0.f, 0.f, 0.f, 0.f);
        }
    };
    auto loadB = [&](int kt, float* vb) {
#pragma unroll
        for (int r = 0; r < 6; ++r) {
            int idx = tid + r * 256;      // 0..1535 = 16*96
            int kl = idx / BN, c = idx % BN;
            vb[r] = __ldg(B + (size_t)(kt * BK + kl) * BN + c);
        }
    };
    auto storeT = [&](int buf, const float4* va, const float* vb) {
#pragma unroll
        for (int r = 0; r < 2; ++r) {
            int row = aRow + r * 64, kl = aQ * 4;
            As[buf][kl + 0][row] = va[r].x;
            As[buf][kl + 1][row] = va[r].y;
            As[buf][kl + 2][row] = va[r].z;
            As[buf][kl + 3][row] = va[r].w;
        }
#pragma unroll
        for (int r = 0; r < 6; ++r) {
            int idx = tid + r * 256;
            Bs[buf][idx / BN][idx % BN] = vb[r];
        }
    };

    const int nK = K / BK;   // 16
    loadA(0, pa); loadB(0, pb);
    storeT(0, pa, pb);
    __syncthreads();

    for (int kt = 0; kt < nK; ++kt) {
        int cur = kt & 1;
        if (kt + 1 < nK) { loadA(kt + 1, pa); loadB(kt + 1, pb); }
#pragma unroll
        for (int k = 0; k < BK; ++k) {
            float4 a0 = *(const float4*)&As[cur][k][tr * 8];
            float4 a1 = *(const float4*)&As[cur][k][tr * 8 + 4];
            float ra[8] = {a0.x, a0.y, a0.z, a0.w, a1.x, a1.y, a1.z, a1.w};
            float rb[6];
#pragma unroll
            for (int j = 0; j < 6; ++j) rb[j] = Bs[cur][k][tc * 6 + j];
#pragma unroll
            for (int i = 0; i < 8; ++i)
#pragma unroll
                for (int j = 0; j < 6; ++j) acc[i][j] += ra[i] * rb[j];
        }
        if (kt + 1 < nK) storeT(1 - cur, pa, pb);
        __syncthreads();
    }

#pragma unroll
    for (int i = 0; i < 8; ++i) {
        int grow = m0 + tr * 8 + i;
        if (grow >= M) continue;
#pragma unroll
        for (int j = 0; j < 6; ++j) {
            int gcol = tc * 6 + j;
            float* dst = (gcol < NCP) ? (hl + (size_t)grow * NCP + gcol)
                                      : (hr + (size_t)grow * NCP + (gcol - NCP));
            *dst = acc[i][j];
        }
    }
}

// ---------------------------------------------------------------------------
// out[n,c] = hr[n,c] + b2[c] + agg2[n,c] * invdeg[n]   (c < 47)
__global__ void finalize(const float* __restrict__ hr,
                         const float* __restrict__ agg2,
                         const float* __restrict__ invdeg,
                         const float* __restrict__ b2,
                         float* __restrict__ out) {
    int i = blockIdx.x * blockDim.x + threadIdx.x;
    if (i >= N_NODES * NCP) return;
    int node = i / NCP, c = i % NCP;
    if (c >= N_CLASSES) return;
    out[(size_t)node * N_CLASSES + c] =
        hr[i] + __ldg(b2 + c) + agg2[i] * __ldg(invdeg + node);
}

// ---------------------------------------------------------------------------
extern "C" void kernel_launch(void* const* d_in, const int* in_sizes, int n_in,
                              void* d_out, int out_size) {
    const float* x   = (const float*)d_in[0];
    const int*   ei  = (const int*)  d_in[1];
    const float* Wl1 = (const float*)d_in[2];
    const float* Wr1 = (const float*)d_in[3];
    const float* b1  = (const float*)d_in[4];
    const float* Wl2 = (const float*)d_in[5];
    const float* Wr2 = (const float*)d_in[6];
    const float* b2  = (const float*)d_in[7];
    float* out = (float*)d_out;

    const int* src = ei;
    const int* dst = ei + N_EDGES;

    float *agg1, *deg, *h, *hl, *hr, *agg2, *wcat;
    cudaGetSymbolAddress((void**)&agg1, g_agg1);
    cudaGetSymbolAddress((void**)&deg,  g_deg);
    cudaGetSymbolAddress((void**)&h,    g_h);
    cudaGetSymbolAddress((void**)&hl,   g_hl);
    cudaGetSymbolAddress((void**)&hr,   g_hr);
    cudaGetSymbolAddress((void**)&agg2, g_agg2);
    cudaGetSymbolAddress((void**)&wcat, g_wcat);

    // 1. zero accumulators + pack layer-2 weights
    {
        int n4 = N_NODES * N_FEAT / 4;
        zero_kernel<<<(n4 + 511) / 512, 512>>>((float4*)agg1, n4);
        n4 = N_NODES * NCP / 4;
        zero_kernel<<<(n4 + 511) / 512, 512>>>((float4*)agg2, n4);
        n4 = N_NODES / 4;
        zero_kernel<<<(n4 + 511) / 512, 512>>>((float4*)deg, n4);
        pack_wcat<<<(HIDN * NW2 + 255) / 256, 256>>>(Wl2, Wr2, wcat);
    }

    // 2. layer-1 scatter (counts degree)
    {
        long long warps = (N_EDGES + EPW - 1) / EPW;
        long long threads = warps * 32;
        int blocks = (int)((threads + 511) / 512);
        scatter_add_128<<<blocks, 512>>>(x, src, dst, agg1, deg, N_EDGES);
    }

    // 3. deg -> 1/max(deg,1)
    invdeg_kernel<<<(N_NODES + 255) / 256, 256>>>(deg, N_NODES);

    // 4. layer-1 fused GEMM -> h
    {
        dim3 grid((N_NODES + 127) / 128, HIDN / 128);
        sage_gemm1<<<grid, 256>>>(agg1, x, deg, Wl1, Wr1, b1, h, N_NODES);
    }

    // 5. combined layer-2 GEMM -> hl, hr
    {
        dim3 grid((N_NODES + 127) / 128, 1);
        sage_gemm2<<<grid, 256>>>(h, wcat, hl, hr, N_NODES);
    }

    // 6. layer-2 scatter on 48-wide hl
    {
        int half = (N_EDGES / 2) * 12;
        scatter_add_48<<<(half + 511) / 512, 512>>>(hl, src, dst, agg2, N_EDGES);
    }

    // 7. finalize: out = hr + b2 + agg2*invdeg
    finalize<<<(N_NODES * NCP + 511) / 512, 512>>>(hr, agg2, deg, b2, out);
}